// round 6
// baseline (speedup 1.0000x reference)
#include <cuda_runtime.h>

// Neural 2D min-sum LDPC decoder, (3,6)-regular layered graph.
// TWO codewords per CTA: msg2[l*NV + v] is a float2 holding the edge message for
// codeword pair (.x, .y). Entire state (3*8192 float2 = 192KB) smem-resident for
// all T iterations; the random check-side gather costs ONE LDS.64 per edge for
// both codewords. In-place update (per layer each variable is in exactly one
// check). Check c, layer l owns edges e = l*NV + 2c + {0,1} (edge_c = i>>1).

#define NV 8192
#define MC 4096
#define NL 3
#define TPB 1024
#define VPT (NV / TPB)    // 8 consecutive variables per thread
#define CPT (MC / TPB)    // 4 checks per thread (strided)
#define SMEM_BYTES (NL * NV * 8)   // 192KB

// Multiset 2-min min-sum core on sign-magnitude bits; exactly reproduces the
// reference min1/min2/argmin + sign-product semantics (incl. ties and zeros).
__device__ __forceinline__ void minsum6(const unsigned u[6], float bt, unsigned res[6])
{
    unsigned a0 = u[0] & 0x7fffffffu, a1 = u[1] & 0x7fffffffu;
    unsigned a2 = u[2] & 0x7fffffffu, a3 = u[3] & 0x7fffffffu;
    unsigned a4 = u[4] & 0x7fffffffu, a5 = u[5] & 0x7fffffffu;
    unsigned xs = (u[0] ^ u[1]) ^ (u[2] ^ u[3]) ^ (u[4] ^ u[5]);

    unsigned lo01 = min(a0, a1), hi01 = max(a0, a1);
    unsigned lo23 = min(a2, a3), hi23 = max(a2, a3);
    unsigned lo45 = min(a4, a5), hi45 = max(a4, a5);
    unsigned m1a  = min(lo01, lo23);
    unsigned m2a  = min(max(lo01, lo23), min(hi01, hi23));
    unsigned m1   = min(m1a, lo45);
    unsigned m2   = min(max(m1a, lo45), min(m2a, hi45));
    m2 = (m1 == 0u) ? 0u : m2;   // exact zero => sign product 0 => all c2v = 0

    unsigned b1 = __float_as_uint(bt * __uint_as_float(m1));
    unsigned b2 = __float_as_uint(bt * __uint_as_float(m2));

    unsigned as[6] = {a0, a1, a2, a3, a4, a5};
#pragma unroll
    for (int p = 0; p < 6; p++) {
        unsigned mag = (as[p] == m1) ? b2 : b1;          // ties => b1==b2
        res[p] = mag ^ ((xs ^ u[p]) & 0x80000000u);
    }
}

__global__ __launch_bounds__(TPB, 1)
void bp_kernel2(const float* __restrict__ llr,
                const int*   __restrict__ edge_v,
                const float* __restrict__ beta,
                const float* __restrict__ alpha,
                float* __restrict__ out_f,
                int*   __restrict__ out_i,
                int B, int T, int mode)
{
    extern __shared__ float2 msg2[];   // [NL*NV]

    const int tid = threadIdx.x;
    const int vb  = tid * VPT;

    // Register-resident check->var table (graph fixed).
    unsigned pk[CPT][NL];
#pragma unroll
    for (int k = 0; k < CPT; k++) {
        int c = tid + k * TPB;
#pragma unroll
        for (int l = 0; l < NL; l++) {
            unsigned v0 = (unsigned)edge_v[l * NV + 2 * c];
            unsigned v1 = (unsigned)edge_v[l * NV + 2 * c + 1];
            pk[k][l] = v0 | (v1 << 16);
        }
    }

    const int P = (B + 1) >> 1;   // codeword pairs
    for (int pr = blockIdx.x; pr < P; pr += gridDim.x) {
        const int cw0 = 2 * pr;
        const int cw1 = cw0 + 1;
        const bool has1 = (cw1 < B);

        // Channel LLRs for both codewords (coalesced float4 per row).
        float2 va[VPT];
#pragma unroll
        for (int g = 0; g < VPT / 4; g++) {
            float4 l0 = *(const float4*)(llr + (size_t)cw0 * NV + vb + 4 * g);
            float4 l1 = has1 ? *(const float4*)(llr + (size_t)cw1 * NV + vb + 4 * g) : l0;
            va[4 * g + 0] = make_float2(l0.x, l1.x);
            va[4 * g + 1] = make_float2(l0.y, l1.y);
            va[4 * g + 2] = make_float2(l0.z, l1.z);
            va[4 * g + 3] = make_float2(l0.w, l1.w);
        }

        // v2c init = llr at each edge.
#pragma unroll
        for (int l = 0; l < NL; l++)
#pragma unroll
            for (int j = 0; j < VPT; j++)
                msg2[l * NV + vb + j] = va[j];
        __syncthreads();

        for (int t = 0; t < T; t++) {
            float bt = __ldg(beta + t);
            float at = __ldg(alpha + t);

            // ---------- check phase: v2c -> c2v (in place, both codewords) ----------
#pragma unroll 1
            for (int k = 0; k < CPT; k++) {
                int vi[6];
#pragma unroll
                for (int l = 0; l < NL; l++) {
                    vi[2 * l]     = (int)(pk[k][l] & 0xFFFFu);
                    vi[2 * l + 1] = (int)(pk[k][l] >> 16);
                }
                float2 w[6];
#pragma unroll
                for (int p = 0; p < 6; p++)
                    w[p] = msg2[(p >> 1) * NV + vi[p]];   // one LDS.64 per edge

                unsigned ux[6], uy[6], rx[6], ry[6];
#pragma unroll
                for (int p = 0; p < 6; p++) {
                    ux[p] = __float_as_uint(w[p].x);
                    uy[p] = __float_as_uint(w[p].y);
                }
                minsum6(ux, bt, rx);
                minsum6(uy, bt, ry);
#pragma unroll
                for (int p = 0; p < 6; p++)
                    msg2[(p >> 1) * NV + vi[p]] =
                        make_float2(__uint_as_float(rx[p]), __uint_as_float(ry[p]));
            }
            __syncthreads();

            // ---------- variable phase: c2v -> v2c (skip after last iter) ----------
            if (t + 1 < T) {
#pragma unroll
                for (int g = 0; g < VPT / 2; g++) {       // float4 = 2 vars x 2 cw
                    int v = vb + 2 * g;
                    float4 c0 = *(float4*)(msg2 + v);
                    float4 c1 = *(float4*)(msg2 + NV + v);
                    float4 c2 = *(float4*)(msg2 + 2 * NV + v);
                    float2 b0 = va[2 * g], b1v = va[2 * g + 1];
                    float4 n0, n1, n2;
                    { float sv = c0.x + c1.x + c2.x;
                      n0.x = b0.x + at * (sv - c0.x); n1.x = b0.x + at * (sv - c1.x); n2.x = b0.x + at * (sv - c2.x); }
                    { float sv = c0.y + c1.y + c2.y;
                      n0.y = b0.y + at * (sv - c0.y); n1.y = b0.y + at * (sv - c1.y); n2.y = b0.y + at * (sv - c2.y); }
                    { float sv = c0.z + c1.z + c2.z;
                      n0.z = b1v.x + at * (sv - c0.z); n1.z = b1v.x + at * (sv - c1.z); n2.z = b1v.x + at * (sv - c2.z); }
                    { float sv = c0.w + c1.w + c2.w;
                      n0.w = b1v.y + at * (sv - c0.w); n1.w = b1v.y + at * (sv - c1.w); n2.w = b1v.y + at * (sv - c2.w); }
                    *(float4*)(msg2 + v)          = n0;
                    *(float4*)(msg2 + NV + v)     = n1;
                    *(float4*)(msg2 + 2 * NV + v) = n2;
                }
                __syncthreads();
            }
        }

        // ---------- posterior + hard decision (both codewords) ----------
#pragma unroll
        for (int j = 0; j < VPT; j++) {
            int v = vb + j;
            float2 c0 = msg2[v];
            float2 c1 = msg2[NV + v];
            float2 c2 = msg2[2 * NV + v];
            float p0 = va[j].x + (c0.x + c1.x + c2.x);
            float p1 = va[j].y + (c0.y + c1.y + c2.y);
            size_t i0 = (size_t)cw0 * NV + v;
            size_t i1 = (size_t)cw1 * NV + v;
            if (mode) {
                out_f[i0] = (p0 < 0.0f) ? 1.0f : 0.0f;
                out_f[(size_t)B * NV + i0] = p0;
                if (has1) {
                    out_f[i1] = (p1 < 0.0f) ? 1.0f : 0.0f;
                    out_f[(size_t)B * NV + i1] = p1;
                }
            } else {
                out_i[i0] = (p0 < 0.0f) ? 1 : 0;
                if (has1) out_i[i1] = (p1 < 0.0f) ? 1 : 0;
            }
        }
        __syncthreads();   // protect msg2 before next pair reuses it
    }
}

extern "C" void kernel_launch(void* const* d_in, const int* in_sizes, int n_in,
                              void* d_out, int out_size) {
    // metadata order: llr [B,N] f32, edge_v [E] i32, edge_c [E] i32 (implicit),
    // beta [T] f32, alpha [T] f32
    const float* llr    = (const float*)d_in[0];
    const int*   edge_v = (const int*)  d_in[1];
    const float* beta   = (const float*)d_in[3];
    const float* alpha  = (const float*)d_in[4];

    int B = in_sizes[0] / NV;
    int T = in_sizes[3];
    int mode = (out_size >= 2 * B * NV) ? 1 : 0;
    int P = (B + 1) / 2;

    cudaFuncSetAttribute((const void*)bp_kernel2,
                         cudaFuncAttributeMaxDynamicSharedMemorySize, SMEM_BYTES);
    bp_kernel2<<<P, TPB, SMEM_BYTES>>>(llr, edge_v, beta, alpha,
                                       (float*)d_out, (int*)d_out, B, T, mode);
}

// round 7
// speedup vs baseline: 1.5893x; 1.5893x over previous
#include <cuda_runtime.h>

// Neural 2D min-sum LDPC decoder, (3,6)-regular layered graph.
// One CTA per codeword; edge state (3*8192 floats = 96KB) smem-resident for all
// T iterations. msg[l*NV + v]: v2c after var phase, c2v after check phase
// (in-place; per layer each variable belongs to exactly one check).
// Check c, layer l owns edges e = l*NV + 2c + {0,1} (edge_c = i>>1 by construction).
//
// Memory layout lesson (R5/R6): the binding resource is shared-memory
// wavefronts. Var phase MUST be strided scalar (tid + k*TPB -> 4B coalesced,
// 1 phase/warp-request); float4/float2 variants double conflict phases.

#define NV 8192
#define MC 4096
#define NL 3
#define TPB 1024
#define VPT (NV / TPB)    // 8 strided variables per thread
#define CPT (MC / TPB)    // 4 checks per thread (strided)
#define SMEM_BYTES (NL * NV * 4)

// Multiset 2-min min-sum core on sign-magnitude bits; exactly reproduces the
// reference min1/min2/argmin + sign-product semantics (incl. ties and zeros).
// (validated rel_err==0.0 in R5/R6 benches)
__device__ __forceinline__ void minsum6(const unsigned u[6], float bt, unsigned res[6])
{
    unsigned a0 = u[0] & 0x7fffffffu, a1 = u[1] & 0x7fffffffu;
    unsigned a2 = u[2] & 0x7fffffffu, a3 = u[3] & 0x7fffffffu;
    unsigned a4 = u[4] & 0x7fffffffu, a5 = u[5] & 0x7fffffffu;
    unsigned xs = (u[0] ^ u[1]) ^ (u[2] ^ u[3]) ^ (u[4] ^ u[5]);

    // nonnegative float bits order as unsigned ints
    unsigned lo01 = min(a0, a1), hi01 = max(a0, a1);
    unsigned lo23 = min(a2, a3), hi23 = max(a2, a3);
    unsigned lo45 = min(a4, a5), hi45 = max(a4, a5);
    unsigned m1a  = min(lo01, lo23);
    unsigned m2a  = min(max(lo01, lo23), min(hi01, hi23));
    unsigned m1   = min(m1a, lo45);
    unsigned m2   = min(max(m1a, lo45), min(m2a, hi45));
    m2 = (m1 == 0u) ? 0u : m2;   // exact zero => sign product 0 => all c2v = 0

    unsigned b1 = __float_as_uint(bt * __uint_as_float(m1));
    unsigned b2 = __float_as_uint(bt * __uint_as_float(m2));

    unsigned as[6] = {a0, a1, a2, a3, a4, a5};
#pragma unroll
    for (int p = 0; p < 6; p++) {
        unsigned mag = (as[p] == m1) ? b2 : b1;          // ties => b1==b2
        res[p] = mag ^ ((xs ^ u[p]) & 0x80000000u);
    }
}

__global__ __launch_bounds__(TPB, 1)
void bp_kernel(const float* __restrict__ llr,
               const int*   __restrict__ edge_v,
               const float* __restrict__ beta,
               const float* __restrict__ alpha,
               float* __restrict__ out_f,
               int*   __restrict__ out_i,
               int B, int T, int mode)
{
    extern __shared__ float msg[];   // [NL*NV]

    const int tid = threadIdx.x;

    // Register-resident check->var table (graph fixed across codewords/iters).
    unsigned pk[CPT][NL];
#pragma unroll
    for (int k = 0; k < CPT; k++) {
        int c = tid + k * TPB;
#pragma unroll
        for (int l = 0; l < NL; l++) {
            unsigned v0 = (unsigned)edge_v[l * NV + 2 * c];
            unsigned v1 = (unsigned)edge_v[l * NV + 2 * c + 1];
            pk[k][l] = v0 | (v1 << 16);
        }
    }

    for (int cw = blockIdx.x; cw < B; cw += gridDim.x) {
        // Channel LLRs: strided, coalesced.
        float llrv[VPT];
#pragma unroll
        for (int k = 0; k < VPT; k++)
            llrv[k] = llr[(size_t)cw * NV + tid + k * TPB];

        // v2c init = llr at each edge (coalesced scalar stores).
#pragma unroll
        for (int l = 0; l < NL; l++)
#pragma unroll
            for (int k = 0; k < VPT; k++)
                msg[l * NV + tid + k * TPB] = llrv[k];
        __syncthreads();

        for (int t = 0; t < T; t++) {
            float bt = __ldg(beta + t);
            float at = __ldg(alpha + t);

            // ---------- check phase: v2c -> c2v (in place) ----------
#pragma unroll 1
            for (int k = 0; k < CPT; k++) {
                int vi[6];
#pragma unroll
                for (int l = 0; l < NL; l++) {
                    vi[2 * l]     = (int)(pk[k][l] & 0xFFFFu);
                    vi[2 * l + 1] = (int)(pk[k][l] >> 16);
                }
                unsigned u[6];
#pragma unroll
                for (int p = 0; p < 6; p++)
                    u[p] = __float_as_uint(msg[(p >> 1) * NV + vi[p]]);  // random LDS.32

                unsigned r[6];
                minsum6(u, bt, r);
#pragma unroll
                for (int p = 0; p < 6; p++)
                    msg[(p >> 1) * NV + vi[p]] = __uint_as_float(r[p]); // random STS.32
            }
            __syncthreads();

            // ---------- variable phase: c2v -> v2c (skip after last iter) ----------
            if (t + 1 < T) {
#pragma unroll
                for (int k = 0; k < VPT; k++) {
                    int v = tid + k * TPB;           // coalesced, conflict-free
                    float c0 = msg[v];
                    float c1 = msg[NV + v];
                    float c2 = msg[2 * NV + v];
                    float sv = c0 + c1 + c2;
                    float base = llrv[k];
                    msg[v]          = base + at * (sv - c0);
                    msg[NV + v]     = base + at * (sv - c1);
                    msg[2 * NV + v] = base + at * (sv - c2);
                }
                __syncthreads();
            }
        }

        // ---------- posterior + hard decision ----------
#pragma unroll
        for (int k = 0; k < VPT; k++) {
            int v = tid + k * TPB;
            float post = llrv[k] + (msg[v] + msg[NV + v] + msg[2 * NV + v]);
            size_t idx = (size_t)cw * NV + v;
            if (mode) {
                // out = [decoded_bits (as f32 0/1) | posterior], each [B,N]
                out_f[idx] = (post < 0.0f) ? 1.0f : 0.0f;
                out_f[(size_t)B * NV + idx] = post;
            } else {
                out_i[idx] = (post < 0.0f) ? 1 : 0;
            }
        }
        __syncthreads();   // protect msg before next codeword reuses it
    }
}

extern "C" void kernel_launch(void* const* d_in, const int* in_sizes, int n_in,
                              void* d_out, int out_size) {
    // metadata order: llr [B,N] f32, edge_v [E] i32, edge_c [E] i32 (implicit),
    // beta [T] f32, alpha [T] f32
    const float* llr    = (const float*)d_in[0];
    const int*   edge_v = (const int*)  d_in[1];
    const float* beta   = (const float*)d_in[3];
    const float* alpha  = (const float*)d_in[4];

    int B = in_sizes[0] / NV;
    int T = in_sizes[3];
    int mode = (out_size >= 2 * B * NV) ? 1 : 0;

    cudaFuncSetAttribute((const void*)bp_kernel,
                         cudaFuncAttributeMaxDynamicSharedMemorySize, SMEM_BYTES);
    bp_kernel<<<B, TPB, SMEM_BYTES>>>(llr, edge_v, beta, alpha,
                                      (float*)d_out, (int*)d_out, B, T, mode);
}